// round 14
// baseline (speedup 1.0000x reference)
#include <cuda_runtime.h>
#include <math.h>
#include <stdint.h>

#define N_NODES 100000
#define D 128
#define E_MAX 1600000
#define LN_EPS 1e-5f
#define N_TILES 782            // ceil(100000/128)
#define N_SLICES 4

// Scratch (allocation-free rule: __device__ globals)
__device__ float g_agg[N_NODES * D];     // normalized mean aggregation
__device__ int   g_cnt[N_NODES];
__device__ int   g_off[N_NODES + 1];
__device__ int   g_pos[N_NODES];
__device__ int   g_csr[E_MAX];
__device__ int   g_bsum[128];
__device__ uint2 g_wsplit[8 * 2048];     // W as fp16 pairs, GEMM smem layout

__device__ __forceinline__ float gelu_exact(float t) {
    return 0.5f * t * (1.0f + erff(t * 0.70710678118654752440f));
}

__device__ __forceinline__ uint32_t smem_u32(const void* p) {
    uint32_t a;
    asm("{ .reg .u64 t; cvta.to.shared.u64 t, %1; cvt.u32.u64 %0, t; }"
        : "=r"(a) : "l"(p));
    return a;
}
// pack {hi_elem -> high 16, lo_elem -> low 16} as fp16x2
__device__ __forceinline__ uint32_t cvt_f16x2(float hi_elem, float lo_elem) {
    uint32_t r;
    asm("{ .reg .b16 h, l;\n\t"
        "cvt.rn.f16.f32 h, %1;\n\t"
        "cvt.rn.f16.f32 l, %2;\n\t"
        "mov.b32 %0, {l, h}; }"
        : "=r"(r) : "f"(hi_elem), "f"(lo_elem));
    return r;
}

// ---------------------------------------------------------------------------
// Phase 0 (fused): zero g_cnt + precompute W as fp16 pairs in GEMM smem layout.
// ---------------------------------------------------------------------------
__global__ void prep_kernel(const float* __restrict__ W_l,
                            const float* __restrict__ W_r) {
    int idx = blockIdx.x * blockDim.x + threadIdx.x;
    if (idx < N_NODES) g_cnt[idx] = 0;
    if (idx >= 8 * 128 * 16) return;
    int c = idx >> 11;
    int m = (idx >> 4) & 127;
    int j = idx & 15;
    const float* src = (c < 4) ? W_l : W_r;
    int k0 = (c & 3) * 32 + j * 2;
    float f0 = src[m * 128 + k0];
    float f1 = src[m * 128 + k0 + 1];
    uint32_t hp = cvt_f16x2(f1, f0);       // low16 = f0, high16 = f1
    int ks = j >> 3, jj = j & 7, half = jj >> 2, tig = jj & 3;
    int p = ((ks << 2) + tig) ^ (m & 7);
    int u2 = (c * 16384 + m * 128 + p * 16 + half * 8) >> 3;
    g_wsplit[u2] = make_uint2(hp, 0u);
}

// ---------------------------------------------------------------------------
// Phase 1: CSR build (histogram -> scan -> index scatter)
// ---------------------------------------------------------------------------
__global__ void hist_kernel(const int* __restrict__ ei, int E) {
    int i = blockIdx.x * blockDim.x + threadIdx.x;
    if (i >= E) return;
    int dst = ei[E + i];
    if ((unsigned)dst < N_NODES) atomicAdd(&g_cnt[dst], 1);
}

#define SCAN_B 1024
__global__ void scan_partial_kernel(int n) {
    __shared__ int sdata[SCAN_B];
    int tid = threadIdx.x;
    int i = blockIdx.x * SCAN_B + tid;
    int v = (i < n) ? g_cnt[i] : 0;
    sdata[tid] = v;
    __syncthreads();
    for (int off = 1; off < SCAN_B; off <<= 1) {
        int t = (tid >= off) ? sdata[tid - off] : 0;
        __syncthreads();
        sdata[tid] += t;
        __syncthreads();
    }
    if (i < n) g_off[i] = sdata[tid] - v;   // exclusive within block
    if (tid == SCAN_B - 1) g_bsum[blockIdx.x] = sdata[tid];
}

// Fused: per-block re-scan of the block sums + global offset add.
__global__ void scan_add_kernel(int n, int E, int nb) {
    __shared__ int sbs[128];
    int tid = threadIdx.x;
    if (tid < 128) sbs[tid] = (tid < nb) ? g_bsum[tid] : 0;
    __syncthreads();
    for (int off = 1; off < 128; off <<= 1) {
        int t = (tid < 128 && tid >= off) ? sbs[tid - off] : 0;
        __syncthreads();
        if (tid < 128) sbs[tid] += t;
        __syncthreads();
    }
    int i = blockIdx.x * blockDim.x + tid;
    if (i < n) {
        int b = i / SCAN_B;
        int base = (b == 0) ? 0 : sbs[b - 1];
        int o = g_off[i] + base;
        g_off[i] = o;
        g_pos[i] = o;
    }
    if (i == 0) g_off[n] = E;
}

__global__ void csr_fill_kernel(const int* __restrict__ ei, int E) {
    int i = blockIdx.x * blockDim.x + threadIdx.x;
    if (i >= E) return;
    int dst = ei[E + i];
    int src = ei[i];
    if ((unsigned)dst >= N_NODES || (unsigned)src >= N_NODES) return;
    int p = atomicAdd(&g_pos[dst], 1);
    g_csr[p] = src;
}

// ---------------------------------------------------------------------------
// Phase 2: gather-aggregate (fp32). One warp per node, sliced node range.
// ---------------------------------------------------------------------------
__global__ void __launch_bounds__(256)
aggregate_kernel(const float* __restrict__ x, int node_lo, int node_hi) {
    int node = node_lo + ((blockIdx.x * blockDim.x + threadIdx.x) >> 5);
    int lane = threadIdx.x & 31;
    if (node >= node_hi) return;
    int beg = g_off[node];
    int end = g_off[node + 1];
    float4 acc = make_float4(0.f, 0.f, 0.f, 0.f);
    const float4* x4 = reinterpret_cast<const float4*>(x);

    int e = beg;
    for (; e + 3 < end; e += 4) {
        int s0 = g_csr[e], s1 = g_csr[e + 1], s2 = g_csr[e + 2], s3 = g_csr[e + 3];
        float4 v0 = x4[(size_t)s0 * 32 + lane];
        float4 v1 = x4[(size_t)s1 * 32 + lane];
        float4 v2 = x4[(size_t)s2 * 32 + lane];
        float4 v3 = x4[(size_t)s3 * 32 + lane];
        acc.x += (v0.x + v1.x) + (v2.x + v3.x);
        acc.y += (v0.y + v1.y) + (v2.y + v3.y);
        acc.z += (v0.z + v1.z) + (v2.z + v3.z);
        acc.w += (v0.w + v1.w) + (v2.w + v3.w);
    }
    for (; e < end; e++) {
        float4 v = x4[(size_t)g_csr[e] * 32 + lane];
        acc.x += v.x; acc.y += v.y; acc.z += v.z; acc.w += v.w;
    }
    float rinv = 1.0f / fmaxf((float)(end - beg), 1.0f);
    acc.x *= rinv; acc.y *= rinv; acc.z *= rinv; acc.w *= rinv;
    reinterpret_cast<float4*>(g_agg)[(size_t)node * 32 + lane] = acc;
}

// ---------------------------------------------------------------------------
// Phase 3: single-pass fp16 mma.sync GEMM + bias + GELU + LayerNorm + residual.
// out = LN(gelu([agg | x] @ [W_l | W_r]^T + b_l)) + x
// ---------------------------------------------------------------------------
#define SM_A  0          // 128 rows * 128 B = 16384
#define SM_B  16384      // 128 rows * 128 B = 16384
#define SM_C  0          // reuse: 128 * 132 * 4 = 67584
#define SM_BL 67584
#define SM_GA 68096
#define SM_BE 68608
#define SM_PS 69120      // 256 floats partial sums
#define SM_PSS 70144     // 256 floats partial sumsq
#define SMEM_G 71168

#define MMA_FP16(accp, A0,A1,A2,A3, B0,B1) \
    asm volatile("mma.sync.aligned.m16n8k16.row.col.f32.f16.f16.f32 " \
        "{%0,%1,%2,%3}, {%4,%5,%6,%7}, {%8,%9}, {%0,%1,%2,%3};" \
        : "+f"((accp)[0]), "+f"((accp)[1]), "+f"((accp)[2]), "+f"((accp)[3]) \
        : "r"(A0), "r"(A1), "r"(A2), "r"(A3), "r"(B0), "r"(B1))

__device__ __forceinline__ void lds128(uint32_t addr, uint32_t& r0, uint32_t& r1,
                                       uint32_t& r2, uint32_t& r3) {
    asm volatile("ld.shared.v4.b32 {%0,%1,%2,%3}, [%4];"
                 : "=r"(r0), "=r"(r1), "=r"(r2), "=r"(r3) : "r"(addr));
}
__device__ __forceinline__ void sts64(uint32_t addr, uint32_t a, uint32_t b) {
    asm volatile("st.shared.v2.b32 [%0], {%1,%2};"
                 :: "r"(addr), "r"(a), "r"(b) : "memory");
}

// Store one k-pair (f0 = k even, f1 = k odd) of row m as an fp16 pair.
__device__ __forceinline__ void stage_pair(uint32_t base, int m, int j,
                                           float f0, float f1) {
    int ks   = j >> 3;
    int jj   = j & 7;
    int half = jj >> 2;
    int tig  = jj & 3;
    uint32_t p = (uint32_t)(((ks << 2) + tig) ^ (m & 7));
    uint32_t addr = base + (uint32_t)m * 128 + p * 16 + (uint32_t)half * 8;
    uint32_t hp = cvt_f16x2(f1, f0);       // low 16 = f0, high 16 = f1
    sts64(addr, hp, 0u);
}

__global__ void __launch_bounds__(256, 2)
gemm_tc_kernel(const float* __restrict__ x,
               const float* __restrict__ b_l,
               const float* __restrict__ ln_gamma,
               const float* __restrict__ ln_beta,
               float* __restrict__ out, int tile_base) {
    extern __shared__ char smem[];
    const uint32_t sb = smem_u32(smem);
    const int tid   = threadIdx.x;
    const int lane  = tid & 31;
    const int wid   = tid >> 5;
    const int g     = lane >> 2;
    const int tig   = lane & 3;
    const int warpM = wid & 3;
    const int warpN = wid >> 2;
    const int row0  = (tile_base + blockIdx.x) * 128;

    if (tid < 128) {
        ((float*)(smem + SM_BL))[tid] = b_l[tid];
        ((float*)(smem + SM_GA))[tid] = ln_gamma[tid];
        ((float*)(smem + SM_BE))[tid] = ln_beta[tid];
    }

    float acc[2][8][4];
    #pragma unroll
    for (int mt = 0; mt < 2; mt++)
        #pragma unroll
        for (int nt = 0; nt < 8; nt++)
            #pragma unroll
            for (int cc = 0; cc < 4; cc++) acc[mt][nt][cc] = 0.f;

    const uint4* wsp = reinterpret_cast<const uint4*>(g_wsplit);

    for (int c = 0; c < 8; c++) {
        // ---- stage A chunk (convert) + B chunk (plain copy) ----
        const float* Asrc = (c < 4) ? (g_agg + c * 32) : (x + (c - 4) * 32);
        #pragma unroll
        for (int it = 0; it < 4; it++) {
            int idx = tid + it * 256;
            int m = idx >> 3, q = idx & 7;
            int row = row0 + m; if (row >= N_NODES) row = N_NODES - 1;
            float4 av = *(const float4*)(Asrc + (size_t)row * D + q * 4);
            stage_pair(sb + SM_A, m, 2 * q,     av.x, av.y);
            stage_pair(sb + SM_A, m, 2 * q + 1, av.z, av.w);
            uint4 bv = wsp[c * 1024 + idx];
            *(uint4*)(smem + SM_B + idx * 16) = bv;
        }
        __syncthreads();

        // ---- compute: 2 k-steps of m16n8k16 fp16, single pass ----
        #pragma unroll
        for (int ks = 0; ks < 2; ks++) {
            uint32_t ah[2][4];
            #pragma unroll
            for (int mt = 0; mt < 2; mt++) {
                int r0w = warpM * 32 + mt * 16 + g;
                uint32_t p0 = (uint32_t)(((ks << 2) + tig) ^ (r0w & 7));
                uint32_t v0, v1, v2, v3;
                lds128(sb + SM_A + (uint32_t)r0w * 128 + p0 * 16, v0, v1, v2, v3);
                ah[mt][0] = v0; ah[mt][2] = v2;
                int r1w = r0w + 8;
                uint32_t p1 = (uint32_t)(((ks << 2) + tig) ^ (r1w & 7));
                lds128(sb + SM_A + (uint32_t)r1w * 128 + p1 * 16, v0, v1, v2, v3);
                ah[mt][1] = v0; ah[mt][3] = v2;
            }
            #pragma unroll
            for (int nt = 0; nt < 8; nt++) {
                int rn = warpN * 64 + nt * 8 + g;
                uint32_t p = (uint32_t)(((ks << 2) + tig) ^ (rn & 7));
                uint32_t bh0, bl0, bh1, bl1;
                lds128(sb + SM_B + (uint32_t)rn * 128 + p * 16, bh0, bl0, bh1, bl1);
                #pragma unroll
                for (int mt = 0; mt < 2; mt++) {
                    MMA_FP16(acc[mt][nt], ah[mt][0], ah[mt][1], ah[mt][2], ah[mt][3], bh0, bh1);
                }
            }
        }
        __syncthreads();
    }

    // ---- dump accumulators into C tile (stride 132 floats) ----
    float* C = (float*)(smem + SM_C);
    #pragma unroll
    for (int mt = 0; mt < 2; mt++) {
        #pragma unroll
        for (int nt = 0; nt < 8; nt++) {
            int row = warpM * 32 + mt * 16 + g;
            int col = warpN * 64 + nt * 8 + 2 * tig;
            *(float2*)(C + row * 132 + col)       = make_float2(acc[mt][nt][0], acc[mt][nt][1]);
            *(float2*)(C + (row + 8) * 132 + col) = make_float2(acc[mt][nt][2], acc[mt][nt][3]);
        }
    }
    __syncthreads();

    // ---- bias + GELU + LN stats ----
    const float* sbl = (const float*)(smem + SM_BL);
    const float* sga = (const float*)(smem + SM_GA);
    const float* sbe = (const float*)(smem + SM_BE);
    float* ps  = (float*)(smem + SM_PS);
    float* pss = (float*)(smem + SM_PSS);

    const int r    = tid & 127;
    const int half = tid >> 7;
    float v[64];
    {
        float s = 0.f, ss = 0.f;
        #pragma unroll
        for (int i = 0; i < 64; i++) {
            int n = half * 64 + i;
            float t = C[r * 132 + n] + sbl[n];
            t = gelu_exact(t);
            v[i] = t;
            s += t;
            ss = fmaf(t, t, ss);
        }
        ps[tid] = s;
        pss[tid] = ss;
    }
    __syncthreads();
    {
        float s  = ps[tid] + ps[tid ^ 128];
        float ss = pss[tid] + pss[tid ^ 128];
        float mu   = s * (1.0f / 128.0f);
        float var  = ss * (1.0f / 128.0f) - mu * mu;
        float rstd = rsqrtf(var + LN_EPS);
        #pragma unroll
        for (int i = 0; i < 64; i++) {
            int n = half * 64 + i;
            C[r * 132 + n] = (v[i] - mu) * rstd * sga[n] + sbe[n];
        }
    }
    __syncthreads();

    // ---- coalesced residual + store ----
    for (int it = 0; it < 16; it++) {
        int idx = tid + it * 256;
        int row = idx >> 5, c4 = idx & 31;
        int grow = row0 + row;
        if (grow < N_NODES) {
            float4 cv = *(float4*)(C + row * 132 + c4 * 4);
            float4 xr = *(const float4*)(x + (size_t)grow * D + c4 * 4);
            cv.x += xr.x; cv.y += xr.y; cv.z += xr.z; cv.w += xr.w;
            *(float4*)(out + (size_t)grow * D + c4 * 4) = cv;
        }
    }
}

// ---------------------------------------------------------------------------
extern "C" void kernel_launch(void* const* d_in, const int* in_sizes, int n_in,
                              void* d_out, int out_size) {
    const float* x     = (const float*)d_in[0];
    const int*   ei    = (const int*)d_in[1];
    const float* W_l   = (const float*)d_in[2];
    const float* b_l   = (const float*)d_in[3];
    const float* W_r   = (const float*)d_in[4];
    const float* gamma = (const float*)d_in[5];
    const float* beta  = (const float*)d_in[6];
    float*       out   = (float*)d_out;

    int E = in_sizes[1] / 2;
    if (E > E_MAX) E = E_MAX;

    // One-time host resources (created on the uncaptured correctness call).
    static cudaStream_t s1 = nullptr;
    static cudaEvent_t evA[N_SLICES], evJoin;
    if (!s1) {
        cudaStreamCreateWithFlags(&s1, cudaStreamNonBlocking);
        for (int q = 0; q < N_SLICES; q++)
            cudaEventCreateWithFlags(&evA[q], cudaEventDisableTiming);
        cudaEventCreateWithFlags(&evJoin, cudaEventDisableTiming);
        cudaFuncSetAttribute(gemm_tc_kernel,
                             cudaFuncAttributeMaxDynamicSharedMemorySize, SMEM_G);
    }

    // Phase 0 + CSR build on the capture (default) stream
    prep_kernel<<<(N_NODES + 255) / 256, 256>>>(W_l, W_r);
    hist_kernel<<<(E + 255) / 256, 256>>>(ei, E);
    int nb = (N_NODES + SCAN_B - 1) / SCAN_B;          // 98 blocks
    scan_partial_kernel<<<nb, SCAN_B>>>(N_NODES);
    scan_add_kernel<<<(N_NODES + 255) / 256, 256>>>(N_NODES, E, nb);
    csr_fill_kernel<<<(E + 255) / 256, 256>>>(ei, E);

    // Sliced aggregate (default stream) + pipelined GEMM (stream s1)
    const int tile_starts[N_SLICES + 1] = {0, 196, 392, 588, N_TILES};
    for (int q = 0; q < N_SLICES; q++) {
        int node_lo = tile_starts[q] * 128;
        int node_hi = tile_starts[q + 1] * 128;
        if (node_hi > N_NODES) node_hi = N_NODES;
        long long athreads = (long long)(node_hi - node_lo) * 32;
        aggregate_kernel<<<(int)((athreads + 255) / 256), 256>>>(x, node_lo, node_hi);
        cudaEventRecord(evA[q], 0);
    }
    for (int q = 0; q < N_SLICES; q++) {
        cudaStreamWaitEvent(s1, evA[q], 0);
        int tiles = tile_starts[q + 1] - tile_starts[q];
        gemm_tc_kernel<<<tiles, 256, SMEM_G, s1>>>(x, b_l, gamma, beta, out,
                                                   tile_starts[q]);
    }
    cudaEventRecord(evJoin, s1);
    cudaStreamWaitEvent(0, evJoin, 0);
}

// round 15
// speedup vs baseline: 1.4186x; 1.4186x over previous
#include <cuda_runtime.h>
#include <math.h>
#include <stdint.h>

#define N_NODES 100000
#define D 128
#define E_MAX 1600000
#define LN_EPS 1e-5f
#define N_TILES 782            // ceil(100000/128)

// Scratch (allocation-free rule: __device__ globals)
__device__ int   g_cnt[N_NODES];
__device__ int   g_off[N_NODES + 1];
__device__ int   g_pos[N_NODES];
__device__ int   g_csr[E_MAX];
__device__ int   g_bsum[128];
__device__ uint4 g_wsplit[8 * 512];          // W fp16 packed, 64KB
__device__ uint4 g_aggh[N_TILES * 2048];     // agg fp16 packed, 25.6MB (zero-init tail)

__device__ __forceinline__ float gelu_exact(float t) {
    return 0.5f * t * (1.0f + erff(t * 0.70710678118654752440f));
}

__device__ __forceinline__ uint32_t smem_u32(const void* p) {
    uint32_t a;
    asm("{ .reg .u64 t; cvta.to.shared.u64 t, %1; cvt.u32.u64 %0, t; }"
        : "=r"(a) : "l"(p));
    return a;
}
// pack {hi_elem -> high 16, lo_elem -> low 16} as fp16x2
__device__ __forceinline__ uint32_t cvt_f16x2(float hi_elem, float lo_elem) {
    uint32_t r;
    asm("{ .reg .b16 h, l;\n\t"
        "cvt.rn.f16.f32 h, %1;\n\t"
        "cvt.rn.f16.f32 l, %2;\n\t"
        "mov.b32 %0, {l, h}; }"
        : "=r"(r) : "f"(hi_elem), "f"(lo_elem));
    return r;
}

// Packed-layout word index within one 32-k chunk (8KB = 2048 words):
// pair j (0..15) of row m: ks=j>>3, jj=j&7, slot s=(jj&3)^(m&3), half=jj>>2
// word = m*16 + s*4 + ks*2 + half
__device__ __forceinline__ int pk_word(int m, int j) {
    int ks = j >> 3, jj = j & 7;
    int s = (jj & 3) ^ (m & 3);
    return m * 16 + s * 4 + ks * 2 + (jj >> 2);
}

// ---------------------------------------------------------------------------
// Phase 0 (fused): zero g_cnt + precompute W fp16 packed in GEMM smem layout.
// ---------------------------------------------------------------------------
__global__ void prep_kernel(const float* __restrict__ W_l,
                            const float* __restrict__ W_r) {
    int idx = blockIdx.x * blockDim.x + threadIdx.x;
    if (idx < N_NODES) g_cnt[idx] = 0;
    if (idx >= 8 * 128 * 16) return;
    int c = idx >> 11;
    int m = (idx >> 4) & 127;
    int j = idx & 15;
    const float* src = (c < 4) ? W_l : W_r;
    int k0 = (c & 3) * 32 + j * 2;
    float f0 = src[m * 128 + k0];
    float f1 = src[m * 128 + k0 + 1];
    reinterpret_cast<uint32_t*>(g_wsplit)[c * 2048 + pk_word(m, j)] =
        cvt_f16x2(f1, f0);     // low16 = f0 (k even), high16 = f1
}

// ---------------------------------------------------------------------------
// Phase 1: CSR build (histogram -> scan -> index scatter)
// ---------------------------------------------------------------------------
__global__ void hist_kernel(const int* __restrict__ ei, int E) {
    int i = (blockIdx.x * blockDim.x + threadIdx.x) * 2;
    if (i >= E) return;
    int2 d = *reinterpret_cast<const int2*>(ei + E + i);
    if ((unsigned)d.x < N_NODES) atomicAdd(&g_cnt[d.x], 1);
    if (i + 1 < E && (unsigned)d.y < N_NODES) atomicAdd(&g_cnt[d.y], 1);
}

#define SCAN_B 1024
__global__ void scan_partial_kernel(int n) {
    __shared__ int sdata[SCAN_B];
    int tid = threadIdx.x;
    int i = blockIdx.x * SCAN_B + tid;
    int v = (i < n) ? g_cnt[i] : 0;
    sdata[tid] = v;
    __syncthreads();
    for (int off = 1; off < SCAN_B; off <<= 1) {
        int t = (tid >= off) ? sdata[tid - off] : 0;
        __syncthreads();
        sdata[tid] += t;
        __syncthreads();
    }
    if (i < n) g_off[i] = sdata[tid] - v;   // exclusive within block
    if (tid == SCAN_B - 1) g_bsum[blockIdx.x] = sdata[tid];
}

// Fused: per-block re-scan of the block sums + global offset add.
__global__ void scan_add_kernel(int n, int E, int nb) {
    __shared__ int sbs[128];
    int tid = threadIdx.x;
    if (tid < 128) sbs[tid] = (tid < nb) ? g_bsum[tid] : 0;
    __syncthreads();
    for (int off = 1; off < 128; off <<= 1) {
        int t = (tid < 128 && tid >= off) ? sbs[tid - off] : 0;
        __syncthreads();
        if (tid < 128) sbs[tid] += t;
        __syncthreads();
    }
    int i = blockIdx.x * blockDim.x + tid;
    if (i < n) {
        int b = i / SCAN_B;
        int base = (b == 0) ? 0 : sbs[b - 1];
        int o = g_off[i] + base;
        g_off[i] = o;
        g_pos[i] = o;
    }
    if (i == 0) g_off[n] = E;
}

__global__ void csr_fill_kernel(const int* __restrict__ ei, int E) {
    int i = (blockIdx.x * blockDim.x + threadIdx.x) * 2;
    if (i >= E) return;
    int2 s2 = *reinterpret_cast<const int2*>(ei + i);
    int2 d2 = *reinterpret_cast<const int2*>(ei + E + i);
    if ((unsigned)d2.x < N_NODES && (unsigned)s2.x < N_NODES) {
        int p = atomicAdd(&g_pos[d2.x], 1);
        g_csr[p] = s2.x;
    }
    if (i + 1 < E && (unsigned)d2.y < N_NODES && (unsigned)s2.y < N_NODES) {
        int p = atomicAdd(&g_pos[d2.y], 1);
        g_csr[p] = s2.y;
    }
}

// ---------------------------------------------------------------------------
// Phase 2: gather-aggregate (fp32 accumulate). One warp per node. No atomics.
// Writes the mean directly as packed fp16 pairs in the GEMM A layout.
// Lane covers features lane*4..+3 => chunk c = lane>>3, pairs j=2q, 2q+1
// (q = lane&7). Tail rows of the last tile stay zero (g_aggh is zero-init).
// ---------------------------------------------------------------------------
__global__ void __launch_bounds__(256)
aggregate_kernel(const float* __restrict__ x) {
    int node = (blockIdx.x * blockDim.x + threadIdx.x) >> 5;
    int lane = threadIdx.x & 31;
    if (node >= N_NODES) return;
    int beg = g_off[node];
    int end = g_off[node + 1];
    float4 acc = make_float4(0.f, 0.f, 0.f, 0.f);
    const float4* x4 = reinterpret_cast<const float4*>(x);

    int e = beg;
    for (; e + 3 < end; e += 4) {
        int s0 = g_csr[e], s1 = g_csr[e + 1], s2 = g_csr[e + 2], s3 = g_csr[e + 3];
        float4 v0 = x4[(size_t)s0 * 32 + lane];
        float4 v1 = x4[(size_t)s1 * 32 + lane];
        float4 v2 = x4[(size_t)s2 * 32 + lane];
        float4 v3 = x4[(size_t)s3 * 32 + lane];
        acc.x += (v0.x + v1.x) + (v2.x + v3.x);
        acc.y += (v0.y + v1.y) + (v2.y + v3.y);
        acc.z += (v0.z + v1.z) + (v2.z + v3.z);
        acc.w += (v0.w + v1.w) + (v2.w + v3.w);
    }
    for (; e < end; e++) {
        float4 v = x4[(size_t)g_csr[e] * 32 + lane];
        acc.x += v.x; acc.y += v.y; acc.z += v.z; acc.w += v.w;
    }
    float rinv = 1.0f / fmaxf((float)(end - beg), 1.0f);

    int tile = node >> 7;
    int m    = node & 127;
    int c    = lane >> 3;
    int q    = lane & 7;
    uint32_t* ah = reinterpret_cast<uint32_t*>(g_aggh) + (size_t)tile * 8192 + c * 2048;
    ah[pk_word(m, 2 * q)]     = cvt_f16x2(acc.y * rinv, acc.x * rinv);
    ah[pk_word(m, 2 * q + 1)] = cvt_f16x2(acc.w * rinv, acc.z * rinv);
}

// ---------------------------------------------------------------------------
// Phase 3: fp16 mma.sync GEMM (packed slots) + bias + GELU + LN + residual.
// out = LN(gelu([agg | x] @ [W_l | W_r]^T + b_l)) + x
// 16B slot = [ (ks0,tig) (ks0,tig+4) (ks1,tig) (ks1,tig+4) ]: one lds128
// feeds BOTH k-steps of a fragment row.
// ---------------------------------------------------------------------------
#define SM_A  0          // 8192
#define SM_B  8192       // 8192
#define SM_C  0          // reuse: 128 * 132 * 4 = 67584
#define SM_BL 67584
#define SM_GA 68096
#define SM_BE 68608
#define SM_PS 69120      // 256 floats partial sums
#define SM_PSS 70144     // 256 floats partial sumsq
#define SMEM_G 71168

#define MMA_FP16(accp, A0,A1,A2,A3, B0,B1) \
    asm volatile("mma.sync.aligned.m16n8k16.row.col.f32.f16.f16.f32 " \
        "{%0,%1,%2,%3}, {%4,%5,%6,%7}, {%8,%9}, {%0,%1,%2,%3};" \
        : "+f"((accp)[0]), "+f"((accp)[1]), "+f"((accp)[2]), "+f"((accp)[3]) \
        : "r"(A0), "r"(A1), "r"(A2), "r"(A3), "r"(B0), "r"(B1))

__device__ __forceinline__ void lds128(uint32_t addr, uint32_t& r0, uint32_t& r1,
                                       uint32_t& r2, uint32_t& r3) {
    asm volatile("ld.shared.v4.b32 {%0,%1,%2,%3}, [%4];"
                 : "=r"(r0), "=r"(r1), "=r"(r2), "=r"(r3) : "r"(addr));
}
__device__ __forceinline__ void sts32(uint32_t addr, uint32_t a) {
    asm volatile("st.shared.b32 [%0], %1;" :: "r"(addr), "r"(a) : "memory");
}

__global__ void __launch_bounds__(256, 2)
gemm_tc_kernel(const float* __restrict__ x,
               const float* __restrict__ b_l,
               const float* __restrict__ ln_gamma,
               const float* __restrict__ ln_beta,
               float* __restrict__ out) {
    extern __shared__ char smem[];
    const uint32_t sb = smem_u32(smem);
    const int tid   = threadIdx.x;
    const int lane  = tid & 31;
    const int wid   = tid >> 5;
    const int g     = lane >> 2;
    const int tig   = lane & 3;
    const int warpM = wid & 3;
    const int warpN = wid >> 2;
    const int row0  = blockIdx.x * 128;

    if (tid < 128) {
        ((float*)(smem + SM_BL))[tid] = b_l[tid];
        ((float*)(smem + SM_GA))[tid] = ln_gamma[tid];
        ((float*)(smem + SM_BE))[tid] = ln_beta[tid];
    }

    float acc[2][8][4];
    #pragma unroll
    for (int mt = 0; mt < 2; mt++)
        #pragma unroll
        for (int nt = 0; nt < 8; nt++)
            #pragma unroll
            for (int cc = 0; cc < 4; cc++) acc[mt][nt][cc] = 0.f;

    const uint32_t frag_slot = (uint32_t)(tig ^ (g & 3)) * 16;  // same for all rows

    for (int c = 0; c < 8; c++) {
        // ---- stage A chunk ----
        if (c < 4) {
            const uint4* asrc = g_aggh + (size_t)blockIdx.x * 2048 + c * 512;
            #pragma unroll
            for (int it = 0; it < 2; it++) {
                int idx = tid + it * 256;
                *(uint4*)(smem + SM_A + idx * 16) = asrc[idx];
            }
        } else {
            const float* Asrc = x + (c - 4) * 32;
            #pragma unroll
            for (int it = 0; it < 4; it++) {
                int idx = tid + it * 256;
                int m = idx >> 3, q = idx & 7;
                int row = row0 + m; if (row >= N_NODES) row = N_NODES - 1;
                float4 av = *(const float4*)(Asrc + (size_t)row * D + q * 4);
                sts32(sb + SM_A + pk_word(m, 2 * q) * 4,     cvt_f16x2(av.y, av.x));
                sts32(sb + SM_A + pk_word(m, 2 * q + 1) * 4, cvt_f16x2(av.w, av.z));
            }
        }
        // ---- stage B chunk (plain copy) ----
        {
            const uint4* bsrc = g_wsplit + c * 512;
            #pragma unroll
            for (int it = 0; it < 2; it++) {
                int idx = tid + it * 256;
                *(uint4*)(smem + SM_B + idx * 16) = bsrc[idx];
            }
        }
        __syncthreads();

        // ---- fragments: one lds128 per row serves both k-steps ----
        uint32_t af[2][2][4];   // [mt][ks][4]
        #pragma unroll
        for (int mt = 0; mt < 2; mt++) {
            int r0w = warpM * 32 + mt * 16 + g;
            uint32_t w0, w1, w2, w3, y0, y1, y2, y3;
            lds128(sb + SM_A + (uint32_t)r0w * 64 + frag_slot, w0, w1, w2, w3);
            lds128(sb + SM_A + (uint32_t)(r0w + 8) * 64 + frag_slot, y0, y1, y2, y3);
            af[mt][0][0] = w0; af[mt][0][1] = y0; af[mt][0][2] = w1; af[mt][0][3] = y1;
            af[mt][1][0] = w2; af[mt][1][1] = y2; af[mt][1][2] = w3; af[mt][1][3] = y3;
        }
        #pragma unroll
        for (int nt = 0; nt < 8; nt++) {
            int rn = warpN * 64 + nt * 8 + g;
            uint32_t b0, b1, b2, b3;
            lds128(sb + SM_B + (uint32_t)rn * 64 + frag_slot, b0, b1, b2, b3);
            #pragma unroll
            for (int mt = 0; mt < 2; mt++) {
                MMA_FP16(acc[mt][nt], af[mt][0][0], af[mt][0][1], af[mt][0][2], af[mt][0][3], b0, b1);
                MMA_FP16(acc[mt][nt], af[mt][1][0], af[mt][1][1], af[mt][1][2], af[mt][1][3], b2, b3);
            }
        }
        __syncthreads();
    }

    // ---- dump accumulators into C tile (stride 132 floats) ----
    float* C = (float*)(smem + SM_C);
    #pragma unroll
    for (int mt = 0; mt < 2; mt++) {
        #pragma unroll
        for (int nt = 0; nt < 8; nt++) {
            int row = warpM * 32 + mt * 16 + g;
            int col = warpN * 64 + nt * 8 + 2 * tig;
            *(float2*)(C + row * 132 + col)       = make_float2(acc[mt][nt][0], acc[mt][nt][1]);
            *(float2*)(C + (row + 8) * 132 + col) = make_float2(acc[mt][nt][2], acc[mt][nt][3]);
        }
    }
    __syncthreads();

    // ---- bias + GELU + LN stats ----
    const float* sbl = (const float*)(smem + SM_BL);
    const float* sga = (const float*)(smem + SM_GA);
    const float* sbe = (const float*)(smem + SM_BE);
    float* ps  = (float*)(smem + SM_PS);
    float* pss = (float*)(smem + SM_PSS);

    const int r    = tid & 127;
    const int half = tid >> 7;
    float v[64];
    {
        float s = 0.f, ss = 0.f;
        #pragma unroll
        for (int i = 0; i < 64; i++) {
            int n = half * 64 + i;
            float t = C[r * 132 + n] + sbl[n];
            t = gelu_exact(t);
            v[i] = t;
            s += t;
            ss = fmaf(t, t, ss);
        }
        ps[tid] = s;
        pss[tid] = ss;
    }
    __syncthreads();
    {
        float s  = ps[tid] + ps[tid ^ 128];
        float ss = pss[tid] + pss[tid ^ 128];
        float mu   = s * (1.0f / 128.0f);
        float var  = ss * (1.0f / 128.0f) - mu * mu;
        float rstd = rsqrtf(var + LN_EPS);
        #pragma unroll
        for (int i = 0; i < 64; i++) {
            int n = half * 64 + i;
            C[r * 132 + n] = (v[i] - mu) * rstd * sga[n] + sbe[n];
        }
    }
    __syncthreads();

    // ---- coalesced residual + store ----
    for (int it = 0; it < 16; it++) {
        int idx = tid + it * 256;
        int row = idx >> 5, c4 = idx & 31;
        int grow = row0 + row;
        if (grow < N_NODES) {
            float4 cv = *(float4*)(C + row * 132 + c4 * 4);
            float4 xr = *(const float4*)(x + (size_t)grow * D + c4 * 4);
            cv.x += xr.x; cv.y += xr.y; cv.z += xr.z; cv.w += xr.w;
            *(float4*)(out + (size_t)grow * D + c4 * 4) = cv;
        }
    }
}

// ---------------------------------------------------------------------------
extern "C" void kernel_launch(void* const* d_in, const int* in_sizes, int n_in,
                              void* d_out, int out_size) {
    const float* x     = (const float*)d_in[0];
    const int*   ei    = (const int*)d_in[1];
    const float* W_l   = (const float*)d_in[2];
    const float* b_l   = (const float*)d_in[3];
    const float* W_r   = (const float*)d_in[4];
    const float* gamma = (const float*)d_in[5];
    const float* beta  = (const float*)d_in[6];
    float*       out   = (float*)d_out;

    int E = in_sizes[1] / 2;
    if (E > E_MAX) E = E_MAX;

    cudaFuncSetAttribute(gemm_tc_kernel,
                         cudaFuncAttributeMaxDynamicSharedMemorySize, SMEM_G);

    // Phase 0 + CSR build
    prep_kernel<<<(N_NODES + 255) / 256, 256>>>(W_l, W_r);
    hist_kernel<<<(E / 2 + 255) / 256, 256>>>(ei, E);
    int nb = (N_NODES + SCAN_B - 1) / SCAN_B;          // 98 blocks
    scan_partial_kernel<<<nb, SCAN_B>>>(N_NODES);
    scan_add_kernel<<<(N_NODES + 255) / 256, 256>>>(N_NODES, E, nb);
    csr_fill_kernel<<<(E / 2 + 255) / 256, 256>>>(ei, E);

    // Gather-aggregate (fp32 accumulate, packed fp16 output)
    long long athreads = (long long)N_NODES * 32;
    aggregate_kernel<<<(int)((athreads + 255) / 256), 256>>>(x);

    // Tensor-core (mma.sync fp16, packed slots) GEMM + fused epilogue
    gemm_tc_kernel<<<N_TILES, 256, SMEM_G>>>(x, b_l, gamma, beta, out);
}